// round 1
// baseline (speedup 1.0000x reference)
#include <cuda_runtime.h>
#include <math.h>

// Problem constants (fixed by the dataset)
#define NPTS   131072
#define WIDTH  128
#define MPAD   132          // padded h row length (floats)
#define MPAD4  33           // padded h row length (float4)

// Scratch (allocation-free rule: __device__ globals)
__device__ float g_phi0[NPTS];
__device__ float g_vals[3 * NPTS];

// ---------------------------------------------------------------------------
// fast tanh: tanh(|x|) = (1 - e)/(1 + e), e = exp(-2|x|)  (never overflows)
// ---------------------------------------------------------------------------
__device__ __forceinline__ float fast_tanh(float x) {
    float ax = fabsf(x);
    float e  = __expf(-2.0f * ax);
    float t  = __fdividef(1.0f - e, 1.0f + e);
    return copysignf(t, x);
}

__device__ __forceinline__ void tanh4(float4& a) {
    a.x = fast_tanh(a.x); a.y = fast_tanh(a.y);
    a.z = fast_tanh(a.z); a.w = fast_tanh(a.w);
}

__device__ __forceinline__ void fma4(float4& a, float s, const float4& w) {
    a.x = fmaf(s, w.x, a.x);
    a.y = fmaf(s, w.y, a.y);
    a.z = fmaf(s, w.z, a.z);
    a.w = fmaf(s, w.w, a.w);
}

// ---------------------------------------------------------------------------
// Generic fused MLP kernel.
//   Block: 256 threads, processes 128 rows (points / point-node rows).
//   smem:  sW 128x128 weights (64KB) | sH 128xMPAD activations | sZ inputs | sB bias
//   Thread tile: 8 rows x 8 cols, cols split as {4*jq..4*jq+3} U {64+4*jq..}
//   is_dp==0: rows are points, input = 5 spherical features, writes g_phi0.
//   is_dp==1: grid = 3*(n/128) blocks node-major; input = [t*nf, sph(5)],
//             writes g_vals[g*NPTS + i].
// ---------------------------------------------------------------------------
__global__ __launch_bounds__(256, 1)
void mlp_kernel(const float* __restrict__ tx,
                const float* __restrict__ W0, const float* __restrict__ b0,
                const float* __restrict__ Wh, const float* __restrict__ bh,
                const float* __restrict__ Wo, const float* __restrict__ bo,
                int in_dim, int is_dp)
{
    extern __shared__ float smem[];
    float* sW = smem;                  // 16384 floats (64 KB)
    float* sH = sW + 16384;            // 128*132 = 16896 floats
    float* sZ = sH + 16896;            // 128*8 = 1024 floats
    float* sB = sZ + 1024;             // 128 floats
    float4* sW4 = (float4*)sW;
    float4* sH4 = (float4*)sH;
    float4* sB4 = (float4*)sB;

    const int tid = threadIdx.x;
    const int jq  = tid & 15;          // 16 column groups
    const int m0  = (tid >> 4) << 3;   // 16 row groups * 8 rows

    int g = 0;
    int i0;
    float nf = 0.0f;                   // (node+1)/2 factor for dp time feature
    if (is_dp) {
        int bpn = gridDim.x / 3;       // blocks per GL node
        g  = blockIdx.x / bpn;
        i0 = (blockIdx.x - g * bpn) << 7;
        const float SQ35 = 0.7745966692414834f;   // sqrt(3/5)
        nf = (g == 0) ? 0.5f * (1.0f - SQ35)
           : (g == 1) ? 0.5f
                      : 0.5f * (1.0f + SQ35);
    } else {
        i0 = blockIdx.x << 7;
    }

    // ---- Stage 0: build inputs (threads 0..127) + load W0/b0 (threads 128..255)
    if (tid < 128) {
        int m = tid;
        float4 p = *(const float4*)(tx + 4 * (i0 + m));  // (t, x, y, z)
        float xx = p.y, yy = p.z, zz = p.w;
        float r2xy = fmaf(xx, xx, yy * yy);
        float r    = sqrtf(fmaf(zz, zz, r2xy) + 1e-8f);
        float rho  = sqrtf(r2xy + 1e-8f);
        float inv_r   = __fdividef(1.0f, r);
        float inv_rho = __fdividef(1.0f, rho);
        float u = __fdividef(r, 1.0f + r);
        float* zr = sZ + m * 8;
        int o = 0;
        if (is_dp) zr[o++] = p.x * nf;     // t_g = t * (node+1)/2
        zr[o++] = u;
        zr[o++] = zz * inv_r;
        zr[o++] = rho * inv_r;
        zr[o++] = xx * inv_rho;
        zr[o++] = yy * inv_rho;
    } else {
        int t2 = tid - 128;
        int nW0 = in_dim * 32;                 // float4 count of W0
        const float4* gw = (const float4*)W0;
        for (int idx = t2; idx < nW0; idx += 128) sW4[idx] = gw[idx];
        sB[t2] = b0[t2];                       // t2 in [0,128)
    }
    __syncthreads();

    float4 acc[8][2];

    // ---- Layer 0: z[in_dim] @ W0 + b0, tanh ----
    {
        float4 bb0 = sB4[jq], bb1 = sB4[16 + jq];
        #pragma unroll
        for (int mi = 0; mi < 8; ++mi) { acc[mi][0] = bb0; acc[mi][1] = bb1; }
        for (int k = 0; k < in_dim; ++k) {
            float4 w0 = sW4[k * 32 + jq];
            float4 w1 = sW4[k * 32 + 16 + jq];
            #pragma unroll
            for (int mi = 0; mi < 8; ++mi) {
                float zv = sZ[(m0 + mi) * 8 + k];
                fma4(acc[mi][0], zv, w0);
                fma4(acc[mi][1], zv, w1);
            }
        }
        #pragma unroll
        for (int mi = 0; mi < 8; ++mi) {
            tanh4(acc[mi][0]); tanh4(acc[mi][1]);
            sH4[(m0 + mi) * MPAD4 + jq]      = acc[mi][0];
            sH4[(m0 + mi) * MPAD4 + 16 + jq] = acc[mi][1];
        }
    }

    // ---- Hidden layers: h = tanh(h @ Wh[l] + bh[l]) ----
    for (int l = 0; l < 3; ++l) {
        __syncthreads();   // sH writes visible; previous sW reads done
        {
            const float4* gw = (const float4*)(Wh + l * 16384);
            #pragma unroll
            for (int idx = tid; idx < 4096; idx += 256) sW4[idx] = gw[idx];
            if (tid < 128) sB[tid] = bh[l * 128 + tid];
        }
        __syncthreads();

        float4 bb0 = sB4[jq], bb1 = sB4[16 + jq];
        #pragma unroll
        for (int mi = 0; mi < 8; ++mi) { acc[mi][0] = bb0; acc[mi][1] = bb1; }

        #pragma unroll 1
        for (int kq = 0; kq < 32; ++kq) {
            float4 w[4][2];
            #pragma unroll
            for (int kk = 0; kk < 4; ++kk) {
                w[kk][0] = sW4[(kq * 4 + kk) * 32 + jq];
                w[kk][1] = sW4[(kq * 4 + kk) * 32 + 16 + jq];
            }
            #pragma unroll
            for (int mi = 0; mi < 8; ++mi) {
                float4 hv = sH4[(m0 + mi) * MPAD4 + kq];
                fma4(acc[mi][0], hv.x, w[0][0]); fma4(acc[mi][1], hv.x, w[0][1]);
                fma4(acc[mi][0], hv.y, w[1][0]); fma4(acc[mi][1], hv.y, w[1][1]);
                fma4(acc[mi][0], hv.z, w[2][0]); fma4(acc[mi][1], hv.z, w[2][1]);
                fma4(acc[mi][0], hv.w, w[3][0]); fma4(acc[mi][1], hv.w, w[3][1]);
            }
        }
        __syncthreads();   // all sH reads for this layer done
        #pragma unroll
        for (int mi = 0; mi < 8; ++mi) {
            tanh4(acc[mi][0]); tanh4(acc[mi][1]);
            sH4[(m0 + mi) * MPAD4 + jq]      = acc[mi][0];
            sH4[(m0 + mi) * MPAD4 + 16 + jq] = acc[mi][1];
        }
    }

    __syncthreads();
    // ---- Output layer: out[m] = h[m] . Wo + bo ----
    if (tid < 32) ((float4*)sZ)[tid] = ((const float4*)Wo)[tid];  // Wo into sZ
    __syncthreads();
    {
        int m    = tid >> 1;
        int half = tid & 1;
        const float4* hr = sH4 + m * MPAD4 + half * 16;
        const float4* wr = ((const float4*)sZ) + half * 16;
        float s = 0.0f;
        #pragma unroll
        for (int q = 0; q < 16; ++q) {
            float4 h = hr[q], w = wr[q];
            s = fmaf(h.x, w.x, s); s = fmaf(h.y, w.y, s);
            s = fmaf(h.z, w.z, s); s = fmaf(h.w, w.w, s);
        }
        s += __shfl_xor_sync(0xffffffffu, s, 1);
        if (half == 0) {
            s += bo[0];
            if (is_dp) g_vals[g * NPTS + i0 + m] = s;
            else       g_phi0[i0 + m] = s;
        }
    }
}

// ---------------------------------------------------------------------------
// Combine: out[i] = phi0[i] + (t/2) * sum_g w_g * vals[g][i]
// ---------------------------------------------------------------------------
__global__ void combine_kernel(const float* __restrict__ tx,
                               float* __restrict__ out, int n)
{
    int i = blockIdx.x * blockDim.x + threadIdx.x;
    if (i >= n) return;
    const float wA = 5.0f / 9.0f;   // nodes +-sqrt(3/5)
    const float wB = 8.0f / 9.0f;   // node 0
    float s = wA * (g_vals[i] + g_vals[2 * NPTS + i]) + wB * g_vals[NPTS + i];
    float t = tx[4 * i];
    out[i] = g_phi0[i] + 0.5f * t * s;
}

// ---------------------------------------------------------------------------
// Launch
// inputs: 0 tx_cart | 1..6 dp_{W0,b0,Wh,bh,Wo,bo} | 7..12 ic_{...}
// ---------------------------------------------------------------------------
extern "C" void kernel_launch(void* const* d_in, const int* in_sizes, int n_in,
                              void* d_out, int out_size)
{
    const float* tx    = (const float*)d_in[0];
    const float* dpW0  = (const float*)d_in[1];
    const float* dpb0  = (const float*)d_in[2];
    const float* dpWh  = (const float*)d_in[3];
    const float* dpbh  = (const float*)d_in[4];
    const float* dpWo  = (const float*)d_in[5];
    const float* dpbo  = (const float*)d_in[6];
    const float* icW0  = (const float*)d_in[7];
    const float* icb0  = (const float*)d_in[8];
    const float* icWh  = (const float*)d_in[9];
    const float* icbh  = (const float*)d_in[10];
    const float* icWo  = (const float*)d_in[11];
    const float* icbo  = (const float*)d_in[12];

    int n = in_sizes[0] / 4;          // 131072
    int nb = n / 128;                 // 1024 blocks

    size_t smem = (size_t)(16384 + 16896 + 1024 + 128) * sizeof(float); // 137728 B
    cudaFuncSetAttribute(mlp_kernel,
                         cudaFuncAttributeMaxDynamicSharedMemorySize, (int)smem);

    // phi0 (ic MLP, 5 input features)
    mlp_kernel<<<nb, 256, smem>>>(tx, icW0, icb0, icWh, icbh, icWo, icbo, 5, 0);
    // dp MLP over 3 GL nodes (node-major rows), 6 input features
    mlp_kernel<<<3 * nb, 256, smem>>>(tx, dpW0, dpb0, dpWh, dpbh, dpWo, dpbo, 6, 1);
    // final Gauss-Legendre combine
    combine_kernel<<<(n + 255) / 256, 256>>>(tx, (float*)d_out, n);
}

// round 9
// speedup vs baseline: 2.6387x; 2.6387x over previous
#include <cuda_runtime.h>
#include <cuda_bf16.h>
#include <cstdint>
#include <math.h>

#define MAX_N 131072

// Scratch + pre-split fragment weights (allocation-free rule)
__device__ float g_phi0[MAX_N];
__device__ float g_vals[3 * MAX_N];
// [net][(layer*8+kt)*512 + nt*32 + lane] = {bh0, bh1, bl0, bl1}
__device__ uint4 g_wfrag[2][12288];

// ---------------------------------------------------------------------------
__device__ __forceinline__ uint32_t pack_bf16(float a, float b) {
    __nv_bfloat162 h = __floats2bfloat162_rn(a, b);
    return *reinterpret_cast<uint32_t*>(&h);
}

__device__ __forceinline__ float fast_tanh(float x) {
    float ax = fabsf(x);
    float e  = __expf(-2.0f * ax);
    float t  = __fdividef(1.0f - e, 1.0f + e);
    return copysignf(t, x);
}

__device__ __forceinline__ void mma_bf16(float c[4],
                                         uint32_t a0, uint32_t a1, uint32_t a2, uint32_t a3,
                                         uint32_t b0, uint32_t b1) {
    asm volatile(
        "mma.sync.aligned.m16n8k16.row.col.f32.bf16.bf16.f32 "
        "{%0,%1,%2,%3}, {%4,%5,%6,%7}, {%8,%9}, {%0,%1,%2,%3};"
        : "+f"(c[0]), "+f"(c[1]), "+f"(c[2]), "+f"(c[3])
        : "r"(a0), "r"(a1), "r"(a2), "r"(a3), "r"(b0), "r"(b1));
}

// ---------------------------------------------------------------------------
// Prep: split Wh (3 x 128 x 128 fp32, [k][n]) into frag-ordered bf16 hi/lo.
// grid = 24 blocks (layer*8 + kt), 512 threads (nt*32 + lane).
// B frag (m16n8k16 col): n = 8*nt + lane/4 ; k = 16*kt + 2*(lane%4) (+1, +8, +9)
// ---------------------------------------------------------------------------
__global__ void prep_kernel(const float* __restrict__ Wh, int net) {
    int bid   = blockIdx.x;          // layer*8 + kt
    int layer = bid >> 3, kt = bid & 7;
    int t     = threadIdx.x;         // nt*32 + lane
    int lane  = t & 31;
    int nn    = 8 * (t >> 5) + (lane >> 2);
    int k0    = 16 * kt + 2 * (lane & 3);
    const float* W = Wh + layer * 16384;

    float w00 = W[k0 * 128 + nn];
    float w01 = W[(k0 + 1) * 128 + nn];
    float w10 = W[(k0 + 8) * 128 + nn];
    float w11 = W[(k0 + 9) * 128 + nn];

    float l00 = w00 - __bfloat162float(__float2bfloat16(w00));
    float l01 = w01 - __bfloat162float(__float2bfloat16(w01));
    float l10 = w10 - __bfloat162float(__float2bfloat16(w10));
    float l11 = w11 - __bfloat162float(__float2bfloat16(w11));

    uint4 out;
    out.x = pack_bf16(w00, w01);
    out.y = pack_bf16(w10, w11);
    out.z = pack_bf16(l00, l01);
    out.w = pack_bf16(l10, l11);
    g_wfrag[net][bid * 512 + t] = out;
}

// ---------------------------------------------------------------------------
// Main persistent kernel. 256 threads = 8 independent warps.
// Each warp processes 16-row chunks; activations live in registers across all
// layers (C-frag layout == A-frag layout). No block syncs in the main loop.
// smem: frag weights 3 layers (192KB) + W0/b0/bh/Wo fp32.
// Templated on IN_DIM/IS_DP so the feature array stays in registers.
// ---------------------------------------------------------------------------
#define SMEM_BYTES (12288 * 16 + (768 + 128 + 384 + 128) * 4)   // 202240

template <int IN_DIM, int IS_DP>
__global__ __launch_bounds__(256, 1)
void mlp_mma_kernel(const float* __restrict__ tx,
                    const float* __restrict__ W0, const float* __restrict__ b0,
                    const float* __restrict__ bh, const float* __restrict__ Wo,
                    const float* __restrict__ bo,
                    int n, int net)
{
    extern __shared__ char sm[];
    uint4* sW  = (uint4*)sm;               // 12288 entries
    float* sW0 = (float*)(sW + 12288);     // IN_DIM*128
    float* sB0 = sW0 + 768;                // 128
    float* sBh = sB0 + 128;                // 384
    float* sWo = sBh + 384;                // 128

    const int tid = threadIdx.x;
    {
        const uint4* src = g_wfrag[net];
        for (int i = tid; i < 12288; i += 256) sW[i] = src[i];
        for (int i = tid; i < IN_DIM * 128; i += 256) sW0[i] = W0[i];
        if (tid < 128) {
            sB0[tid] = b0[tid];
            sWo[tid] = Wo[tid];
            sBh[tid] = bh[tid];
            sBh[128 + tid] = bh[128 + tid];
            sBh[256 + tid] = bh[256 + tid];
        }
    }
    __syncthreads();

    const int warp   = tid >> 5;
    const int lane   = tid & 31;
    const int q2     = 2 * (lane & 3);     // C/A col offset within 8-wide tile
    const int rofs   = lane >> 2;          // row within 16-row chunk (and +8)
    const float bo0  = __ldg(bo);
    const int cpn    = n >> 4;             // 16-row chunks per GL node
    const int nchunks = IS_DP ? 3 * cpn : cpn;
    const int wstep  = gridDim.x * 8;

    // incremental node-index tracking (avoids div in the loop)
    int ch0 = blockIdx.x * 8 + warp;
    int g   = 0;
    if (IS_DP) { while (g < 2 && ch0 >= (g + 1) * cpn) ++g; }

    for (int ch = ch0; ch < nchunks; ch += wstep) {
        int idx = ch;
        float nf = 0.0f;
        if (IS_DP) {
            while (g < 2 && ch >= (g + 1) * cpn) ++g;
            idx = ch - g * cpn;
            const float SQ = 0.7745966692414834f;
            nf = (g == 0) ? 0.5f * (1.0f - SQ) : (g == 1) ? 0.5f : 0.5f * (1.0f + SQ);
        }
        const int rA = (idx << 4) + rofs;             // rows rA and rA+8

        // ---- features for both owned rows (fully unrolled -> registers) ----
        float zA[IN_DIM], zB[IN_DIM];
        #pragma unroll
        for (int half = 0; half < 2; ++half) {
            float* z = half ? zB : zA;
            float4 p = *(const float4*)(tx + 4 * (rA + 8 * half));
            float xx = p.y, yy = p.z, zz = p.w;
            float r2  = fmaf(xx, xx, yy * yy);
            float r   = sqrtf(fmaf(zz, zz, r2) + 1e-8f);
            float rho = sqrtf(r2 + 1e-8f);
            float ir  = __fdividef(1.0f, r);
            float irh = __fdividef(1.0f, rho);
            int o = 0;
            if (IS_DP) z[o++] = p.x * nf;
            z[o++] = __fdividef(r, 1.0f + r);
            z[o++] = zz * ir;
            z[o++] = rho * ir;
            z[o++] = xx * irh;
            z[o++] = yy * irh;
        }

        // ---- layer 0 (scalar fp32): v[nt][{0,1}] rows rA, v[nt][{2,3}] rows rA+8
        float v[16][4];
        #pragma unroll
        for (int nt = 0; nt < 16; ++nt) {
            float2 bb = *(const float2*)(sB0 + 8 * nt + q2);
            v[nt][0] = bb.x; v[nt][1] = bb.y; v[nt][2] = bb.x; v[nt][3] = bb.y;
        }
        #pragma unroll
        for (int k = 0; k < IN_DIM; ++k) {
            float a = zA[k], b = zB[k];
            const float* wr = sW0 + k * 128 + q2;
            #pragma unroll
            for (int nt = 0; nt < 16; ++nt) {
                float2 w = *(const float2*)(wr + 8 * nt);
                v[nt][0] = fmaf(a, w.x, v[nt][0]);
                v[nt][1] = fmaf(a, w.y, v[nt][1]);
                v[nt][2] = fmaf(b, w.x, v[nt][2]);
                v[nt][3] = fmaf(b, w.y, v[nt][3]);
            }
        }
        #pragma unroll
        for (int nt = 0; nt < 16; ++nt)
            #pragma unroll
            for (int j = 0; j < 4; ++j) v[nt][j] = fast_tanh(v[nt][j]);

        // ---- 3 hidden layers on tensor cores (register-resident activations)
        #pragma unroll 1
        for (int l = 0; l < 3; ++l) {
            // split to bf16 hi/lo (A-frag packing: C layout == A layout)
            uint32_t ah[32], al[32];
            #pragma unroll
            for (int nt = 0; nt < 16; ++nt) {
                #pragma unroll
                for (int jj = 0; jj < 2; ++jj) {
                    float a = v[nt][2 * jj], b = v[nt][2 * jj + 1];
                    uint32_t h = pack_bf16(a, b);
                    __nv_bfloat162 hb = *reinterpret_cast<__nv_bfloat162*>(&h);
                    float ra = a - __bfloat162float(hb.x);
                    float rb = b - __bfloat162float(hb.y);
                    ah[nt * 2 + jj] = h;
                    al[nt * 2 + jj] = pack_bf16(ra, rb);
                }
            }
            // accum init = bias
            float c[16][4];
            const float* blp = sBh + l * 128 + q2;
            #pragma unroll
            for (int nt = 0; nt < 16; ++nt) {
                float2 bb = *(const float2*)(blp + 8 * nt);
                c[nt][0] = bb.x; c[nt][1] = bb.y; c[nt][2] = bb.x; c[nt][3] = bb.y;
            }
            const uint4* wl = sW + l * 4096 + lane;
            #pragma unroll
            for (int kt = 0; kt < 8; ++kt) {
                uint32_t A0 = ah[4 * kt], A1 = ah[4 * kt + 1],
                         A2 = ah[4 * kt + 2], A3 = ah[4 * kt + 3];
                uint32_t L0 = al[4 * kt], L1 = al[4 * kt + 1],
                         L2 = al[4 * kt + 2], L3 = al[4 * kt + 3];
                #pragma unroll
                for (int nt = 0; nt < 16; ++nt) {
                    uint4 b = wl[(kt * 16 + nt) * 32];
                    mma_bf16(c[nt], A0, A1, A2, A3, b.x, b.y);   // hi*Whi
                    mma_bf16(c[nt], L0, L1, L2, L3, b.x, b.y);   // lo*Whi
                    mma_bf16(c[nt], A0, A1, A2, A3, b.z, b.w);   // hi*Wlo
                }
            }
            #pragma unroll
            for (int nt = 0; nt < 16; ++nt)
                #pragma unroll
                for (int j = 0; j < 4; ++j) v[nt][j] = fast_tanh(c[nt][j]);
        }

        // ---- output layer: dot with Wo, reduce over the 4 lanes of the group
        float sA = 0.0f, sB = 0.0f;
        #pragma unroll
        for (int nt = 0; nt < 16; ++nt) {
            float2 w = *(const float2*)(sWo + 8 * nt + q2);
            sA = fmaf(v[nt][0], w.x, fmaf(v[nt][1], w.y, sA));
            sB = fmaf(v[nt][2], w.x, fmaf(v[nt][3], w.y, sB));
        }
        sA += __shfl_xor_sync(0xffffffffu, sA, 1);
        sA += __shfl_xor_sync(0xffffffffu, sA, 2);
        sB += __shfl_xor_sync(0xffffffffu, sB, 1);
        sB += __shfl_xor_sync(0xffffffffu, sB, 2);
        if ((lane & 3) == 0) {
            float* dst = IS_DP ? (g_vals + g * n) : g_phi0;
            dst[rA]     = sA + bo0;
            dst[rA + 8] = sB + bo0;
        }
    }
}

// ---------------------------------------------------------------------------
__global__ void combine_kernel(const float* __restrict__ tx,
                               float* __restrict__ out, int n)
{
    int i = blockIdx.x * blockDim.x + threadIdx.x;
    if (i >= n) return;
    const float wA = 5.0f / 9.0f;
    const float wB = 8.0f / 9.0f;
    float s = wA * (g_vals[i] + g_vals[2 * n + i]) + wB * g_vals[n + i];
    float t = tx[4 * i];
    out[i] = g_phi0[i] + 0.5f * t * s;
}

// ---------------------------------------------------------------------------
// inputs: 0 tx | 1..6 dp_{W0,b0,Wh,bh,Wo,bo} | 7..12 ic_{...}
// ---------------------------------------------------------------------------
extern "C" void kernel_launch(void* const* d_in, const int* in_sizes, int n_in,
                              void* d_out, int out_size)
{
    const float* tx   = (const float*)d_in[0];
    const float* dpW0 = (const float*)d_in[1];
    const float* dpb0 = (const float*)d_in[2];
    const float* dpWh = (const float*)d_in[3];
    const float* dpbh = (const float*)d_in[4];
    const float* dpWo = (const float*)d_in[5];
    const float* dpbo = (const float*)d_in[6];
    const float* icW0 = (const float*)d_in[7];
    const float* icb0 = (const float*)d_in[8];
    const float* icWh = (const float*)d_in[9];
    const float* icbh = (const float*)d_in[10];
    const float* icWo = (const float*)d_in[11];
    const float* icbo = (const float*)d_in[12];

    int n = in_sizes[0] / 4;   // 131072

    int smc = 148;
    cudaDeviceGetAttribute(&smc, cudaDevAttrMultiProcessorCount, 0);

    cudaFuncSetAttribute(mlp_mma_kernel<5, 0>,
                         cudaFuncAttributeMaxDynamicSharedMemorySize, SMEM_BYTES);
    cudaFuncSetAttribute(mlp_mma_kernel<6, 1>,
                         cudaFuncAttributeMaxDynamicSharedMemorySize, SMEM_BYTES);

    // pre-split weights into fragment order (net 0 = ic, net 1 = dp)
    prep_kernel<<<24, 512>>>(icWh, 0);
    prep_kernel<<<24, 512>>>(dpWh, 1);

    // ic: phi0, 5 features
    mlp_mma_kernel<5, 0><<<smc, 256, SMEM_BYTES>>>(
        tx, icW0, icb0, icbh, icWo, icbo, n, 0);
    // dp: 3 GL nodes, 6 features
    mlp_mma_kernel<6, 1><<<smc, 256, SMEM_BYTES>>>(
        tx, dpW0, dpb0, dpbh, dpWo, dpbo, n, 1);
    // Gauss-Legendre combine
    combine_kernel<<<(n + 255) / 256, 256>>>(tx, (float*)d_out, n);
}

// round 11
// speedup vs baseline: 2.6498x; 1.0042x over previous
#include <cuda_runtime.h>
#include <cuda_bf16.h>
#include <cstdint>
#include <math.h>

#define MAX_N 131072

// Scratch + pre-split fragment weights (allocation-free rule)
__device__ float g_phi0[MAX_N];
__device__ float g_vals[3 * MAX_N];
// [net][(layer*8+kt)*512 + nt*32 + lane] = {bh0, bh1, bl0, bl1}
__device__ uint4 g_wfrag[2][12288];

// ---------------------------------------------------------------------------
__device__ __forceinline__ uint32_t pack_bf16(float a, float b) {
    __nv_bfloat162 h = __floats2bfloat162_rn(a, b);
    return *reinterpret_cast<uint32_t*>(&h);
}

__device__ __forceinline__ float fast_tanh(float x) {
    float ax = fabsf(x);
    float e  = __expf(-2.0f * ax);
    float t  = __fdividef(1.0f - e, 1.0f + e);
    return copysignf(t, x);
}

__device__ __forceinline__ void mma_bf16(float c[4],
                                         uint32_t a0, uint32_t a1, uint32_t a2, uint32_t a3,
                                         uint32_t b0, uint32_t b1) {
    asm volatile(
        "mma.sync.aligned.m16n8k16.row.col.f32.bf16.bf16.f32 "
        "{%0,%1,%2,%3}, {%4,%5,%6,%7}, {%8,%9}, {%0,%1,%2,%3};"
        : "+f"(c[0]), "+f"(c[1]), "+f"(c[2]), "+f"(c[3])
        : "r"(a0), "r"(a1), "r"(a2), "r"(a3), "r"(b0), "r"(b1));
}

// ---------------------------------------------------------------------------
// Prep: split Wh (3 x 128 x 128 fp32, [k][n]) into frag-ordered bf16 hi/lo.
// grid = 24 blocks (layer*8 + kt), 512 threads (nt*32 + lane).
// B frag (m16n8k16 col): n = 8*nt + lane/4 ; k = 16*kt + 2*(lane%4) (+1, +8, +9)
// ---------------------------------------------------------------------------
__global__ void prep_kernel(const float* __restrict__ Wh, int net) {
    int bid   = blockIdx.x;          // layer*8 + kt
    int layer = bid >> 3, kt = bid & 7;
    int t     = threadIdx.x;         // nt*32 + lane
    int lane  = t & 31;
    int nn    = 8 * (t >> 5) + (lane >> 2);
    int k0    = 16 * kt + 2 * (lane & 3);
    const float* W = Wh + layer * 16384;

    float w00 = W[k0 * 128 + nn];
    float w01 = W[(k0 + 1) * 128 + nn];
    float w10 = W[(k0 + 8) * 128 + nn];
    float w11 = W[(k0 + 9) * 128 + nn];

    float l00 = w00 - __bfloat162float(__float2bfloat16(w00));
    float l01 = w01 - __bfloat162float(__float2bfloat16(w01));
    float l10 = w10 - __bfloat162float(__float2bfloat16(w10));
    float l11 = w11 - __bfloat162float(__float2bfloat16(w11));

    uint4 out;
    out.x = pack_bf16(w00, w01);
    out.y = pack_bf16(w10, w11);
    out.z = pack_bf16(l00, l01);
    out.w = pack_bf16(l10, l11);
    g_wfrag[net][bid * 512 + t] = out;
}

// ---------------------------------------------------------------------------
// Main persistent kernel. 384 threads = 12 independent warps (3 per SMSP) so
// one warp's split/tanh epilogue overlaps the other warps' HMMA phases.
// A-frag hi/lo split happens on the fly inside the kt loop (v[nt] is consumed
// by exactly one kt), cutting peak live registers so 384 threads fit the RF.
// smem: frag weights 3 layers (192KB) + W0/b0/bh/Wo fp32.
// ---------------------------------------------------------------------------
#define SMEM_BYTES (12288 * 16 + (768 + 128 + 384 + 128) * 4)   // 202240
#define NWARP 12
#define NTHR  (NWARP * 32)

template <int IN_DIM, int IS_DP>
__global__ __launch_bounds__(NTHR, 1)
void mlp_mma_kernel(const float* __restrict__ tx,
                    const float* __restrict__ W0, const float* __restrict__ b0,
                    const float* __restrict__ bh, const float* __restrict__ Wo,
                    const float* __restrict__ bo,
                    int n, int net)
{
    extern __shared__ char sm[];
    uint4* sW  = (uint4*)sm;               // 12288 entries
    float* sW0 = (float*)(sW + 12288);     // IN_DIM*128
    float* sB0 = sW0 + 768;                // 128
    float* sBh = sB0 + 128;                // 384
    float* sWo = sBh + 384;                // 128

    const int tid = threadIdx.x;
    {
        const uint4* src = g_wfrag[net];
        for (int i = tid; i < 12288; i += NTHR) sW[i] = src[i];
        for (int i = tid; i < IN_DIM * 128; i += NTHR) sW0[i] = W0[i];
        if (tid < 128) {
            sB0[tid] = b0[tid];
            sWo[tid] = Wo[tid];
            sBh[tid] = bh[tid];
            sBh[128 + tid] = bh[128 + tid];
            sBh[256 + tid] = bh[256 + tid];
        }
    }
    __syncthreads();

    const int warp   = tid >> 5;
    const int lane   = tid & 31;
    const int q2     = 2 * (lane & 3);     // C/A col offset within 8-wide tile
    const int rofs   = lane >> 2;          // row within 16-row chunk (and +8)
    const float bo0  = __ldg(bo);
    const int cpn    = n >> 4;             // 16-row chunks per GL node
    const int nchunks = IS_DP ? 3 * cpn : cpn;
    const int wstep  = gridDim.x * NWARP;

    // incremental node-index tracking (avoids div in the loop)
    int ch0 = blockIdx.x * NWARP + warp;
    int g   = 0;
    if (IS_DP) { while (g < 2 && ch0 >= (g + 1) * cpn) ++g; }

    for (int ch = ch0; ch < nchunks; ch += wstep) {
        int idx = ch;
        float nf = 0.0f;
        if (IS_DP) {
            while (g < 2 && ch >= (g + 1) * cpn) ++g;
            idx = ch - g * cpn;
            const float SQ = 0.7745966692414834f;
            nf = (g == 0) ? 0.5f * (1.0f - SQ) : (g == 1) ? 0.5f : 0.5f * (1.0f + SQ);
        }
        const int rA = (idx << 4) + rofs;             // rows rA and rA+8

        // ---- features for both owned rows (fully unrolled -> registers) ----
        float zA[IN_DIM], zB[IN_DIM];
        #pragma unroll
        for (int half = 0; half < 2; ++half) {
            float* z = half ? zB : zA;
            float4 p = *(const float4*)(tx + 4 * (rA + 8 * half));
            float xx = p.y, yy = p.z, zz = p.w;
            float r2  = fmaf(xx, xx, yy * yy);
            float r   = sqrtf(fmaf(zz, zz, r2) + 1e-8f);
            float rho = sqrtf(r2 + 1e-8f);
            float ir  = __fdividef(1.0f, r);
            float irh = __fdividef(1.0f, rho);
            int o = 0;
            if (IS_DP) z[o++] = p.x * nf;
            z[o++] = __fdividef(r, 1.0f + r);
            z[o++] = zz * ir;
            z[o++] = rho * ir;
            z[o++] = xx * irh;
            z[o++] = yy * irh;
        }

        // ---- layer 0 (scalar fp32): v[nt][{0,1}] rows rA, v[nt][{2,3}] rows rA+8
        float v[16][4];
        #pragma unroll
        for (int nt = 0; nt < 16; ++nt) {
            float2 bb = *(const float2*)(sB0 + 8 * nt + q2);
            v[nt][0] = bb.x; v[nt][1] = bb.y; v[nt][2] = bb.x; v[nt][3] = bb.y;
        }
        #pragma unroll
        for (int k = 0; k < IN_DIM; ++k) {
            float a = zA[k], b = zB[k];
            const float* wr = sW0 + k * 128 + q2;
            #pragma unroll
            for (int nt = 0; nt < 16; ++nt) {
                float2 w = *(const float2*)(wr + 8 * nt);
                v[nt][0] = fmaf(a, w.x, v[nt][0]);
                v[nt][1] = fmaf(a, w.y, v[nt][1]);
                v[nt][2] = fmaf(b, w.x, v[nt][2]);
                v[nt][3] = fmaf(b, w.y, v[nt][3]);
            }
        }
        #pragma unroll
        for (int nt = 0; nt < 16; ++nt)
            #pragma unroll
            for (int j = 0; j < 4; ++j) v[nt][j] = fast_tanh(v[nt][j]);

        // ---- 3 hidden layers on tensor cores (register-resident activations)
        #pragma unroll 1
        for (int l = 0; l < 3; ++l) {
            // accum init = bias
            float c[16][4];
            const float* blp = sBh + l * 128 + q2;
            #pragma unroll
            for (int nt = 0; nt < 16; ++nt) {
                float2 bb = *(const float2*)(blp + 8 * nt);
                c[nt][0] = bb.x; c[nt][1] = bb.y; c[nt][2] = bb.x; c[nt][3] = bb.y;
            }
            const uint4* wl = sW + l * 4096 + lane;
            #pragma unroll
            for (int kt = 0; kt < 8; ++kt) {
                // on-the-fly split of v[2kt], v[2kt+1] into the kt A-fragment
                uint32_t AH[4], AL[4];
                #pragma unroll
                for (int t2 = 0; t2 < 2; ++t2) {
                    int nt = 2 * kt + t2;
                    #pragma unroll
                    for (int jj = 0; jj < 2; ++jj) {
                        float a = v[nt][2 * jj], b = v[nt][2 * jj + 1];
                        uint32_t h = pack_bf16(a, b);
                        __nv_bfloat162 hb = *reinterpret_cast<__nv_bfloat162*>(&h);
                        float ra = a - __bfloat162float(hb.x);
                        float rb = b - __bfloat162float(hb.y);
                        AH[t2 * 2 + jj] = h;
                        AL[t2 * 2 + jj] = pack_bf16(ra, rb);
                    }
                }
                #pragma unroll
                for (int nt = 0; nt < 16; ++nt) {
                    uint4 b = wl[(kt * 16 + nt) * 32];
                    mma_bf16(c[nt], AH[0], AH[1], AH[2], AH[3], b.x, b.y); // hi*Whi
                    mma_bf16(c[nt], AL[0], AL[1], AL[2], AL[3], b.x, b.y); // lo*Whi
                    mma_bf16(c[nt], AH[0], AH[1], AH[2], AH[3], b.z, b.w); // hi*Wlo
                }
            }
            #pragma unroll
            for (int nt = 0; nt < 16; ++nt)
                #pragma unroll
                for (int j = 0; j < 4; ++j) v[nt][j] = fast_tanh(c[nt][j]);
        }

        // ---- output layer: dot with Wo, reduce over the 4 lanes of the group
        float sA = 0.0f, sB = 0.0f;
        #pragma unroll
        for (int nt = 0; nt < 16; ++nt) {
            float2 w = *(const float2*)(sWo + 8 * nt + q2);
            sA = fmaf(v[nt][0], w.x, fmaf(v[nt][1], w.y, sA));
            sB = fmaf(v[nt][2], w.x, fmaf(v[nt][3], w.y, sB));
        }
        sA += __shfl_xor_sync(0xffffffffu, sA, 1);
        sA += __shfl_xor_sync(0xffffffffu, sA, 2);
        sB += __shfl_xor_sync(0xffffffffu, sB, 1);
        sB += __shfl_xor_sync(0xffffffffu, sB, 2);
        if ((lane & 3) == 0) {
            float* dst = IS_DP ? (g_vals + g * n) : g_phi0;
            dst[rA]     = sA + bo0;
            dst[rA + 8] = sB + bo0;
        }
    }
}

// ---------------------------------------------------------------------------
__global__ void combine_kernel(const float* __restrict__ tx,
                               float* __restrict__ out, int n)
{
    int i = blockIdx.x * blockDim.x + threadIdx.x;
    if (i >= n) return;
    const float wA = 5.0f / 9.0f;
    const float wB = 8.0f / 9.0f;
    float s = wA * (g_vals[i] + g_vals[2 * n + i]) + wB * g_vals[n + i];
    float t = tx[4 * i];
    out[i] = g_phi0[i] + 0.5f * t * s;
}

// ---------------------------------------------------------------------------
// inputs: 0 tx | 1..6 dp_{W0,b0,Wh,bh,Wo,bo} | 7..12 ic_{...}
// ---------------------------------------------------------------------------
extern "C" void kernel_launch(void* const* d_in, const int* in_sizes, int n_in,
                              void* d_out, int out_size)
{
    const float* tx   = (const float*)d_in[0];
    const float* dpW0 = (const float*)d_in[1];
    const float* dpb0 = (const float*)d_in[2];
    const float* dpWh = (const float*)d_in[3];
    const float* dpbh = (const float*)d_in[4];
    const float* dpWo = (const float*)d_in[5];
    const float* dpbo = (const float*)d_in[6];
    const float* icW0 = (const float*)d_in[7];
    const float* icb0 = (const float*)d_in[8];
    const float* icWh = (const float*)d_in[9];
    const float* icbh = (const float*)d_in[10];
    const float* icWo = (const float*)d_in[11];
    const float* icbo = (const float*)d_in[12];

    int n = in_sizes[0] / 4;   // 131072

    int smc = 148;
    cudaDeviceGetAttribute(&smc, cudaDevAttrMultiProcessorCount, 0);

    cudaFuncSetAttribute(mlp_mma_kernel<5, 0>,
                         cudaFuncAttributeMaxDynamicSharedMemorySize, SMEM_BYTES);
    cudaFuncSetAttribute(mlp_mma_kernel<6, 1>,
                         cudaFuncAttributeMaxDynamicSharedMemorySize, SMEM_BYTES);

    // pre-split weights into fragment order (net 0 = ic, net 1 = dp)
    prep_kernel<<<24, 512>>>(icWh, 0);
    prep_kernel<<<24, 512>>>(dpWh, 1);

    // ic: phi0, 5 features
    mlp_mma_kernel<5, 0><<<smc, NTHR, SMEM_BYTES>>>(
        tx, icW0, icb0, icbh, icWo, icbo, n, 0);
    // dp: 3 GL nodes, 6 features
    mlp_mma_kernel<6, 1><<<smc, NTHR, SMEM_BYTES>>>(
        tx, dpW0, dpb0, dpbh, dpWo, dpbo, n, 1);
    // Gauss-Legendre combine
    combine_kernel<<<(n + 255) / 256, 256>>>(tx, (float*)d_out, n);
}